// round 1
// baseline (speedup 1.0000x reference)
#include <cuda_runtime.h>
#include <math.h>

#define NB 2
#define NQ 4
#define NH 32
#define NHK 8
#define HD 128
#define DMODEL 4096
#define NCOLS (DMODEL + 1024 + 1024)   // 6144 fused qkv output columns
#define NROWS (NB * NQ)                // 8
#define SMAX 4352
#define NROWS_ATT (NB * NH * NQ)       // 256
#define KSPLIT 16
#define KCH (DMODEL / KSPLIT)          // 256
#define VSPLIT 4

// ---------------- scratch (device globals; no allocation) ----------------
__device__ float g_qkv[NROWS * NCOLS];           // fused q|k|v projection
__device__ float g_cos[SMAX * 64];
__device__ float g_sin[SMAX * 64];
__device__ float g_qr[NB * NH * NQ * HD];        // roped queries [b][h][q][d]
__device__ float g_knew[NB * NHK * NQ * HD];     // roped new keys
__device__ float g_vnew[NB * NHK * NQ * HD];     // new values
__device__ float g_draft[NROWS_ATT * SMAX];      // draft scores [row][s]
__device__ unsigned int g_thrkey[NROWS_ATT];     // top-k threshold (sortable key)
__device__ float g_rowmax[NROWS_ATT];
__device__ float g_num[NROWS_ATT * HD];          // softmax numerator accum
__device__ float g_den[NROWS_ATT];               // softmax denominator accum
__device__ float g_attn[NROWS * DMODEL];         // pre-Wo attention output

// ---------------- zero accumulators each launch ----------------
__global__ void zero_bufs(float* __restrict__ out, int osz) {
    int i = blockIdx.x * 256 + threadIdx.x;
    if (i < NROWS * NCOLS)   g_qkv[i] = 0.f;
    if (i < NROWS_ATT * HD)  g_num[i] = 0.f;
    if (i < NROWS_ATT)       g_den[i] = 0.f;
    if (i < osz)             out[i]  = 0.f;
}

// ---------------- rope tables: cos/sin[pos][i], i = d mod 64 ----------------
__global__ void rope_table(int S) {
    __shared__ float invf[64];
    int t = threadIdx.x;  // 256 threads: 4 positions x 64 freqs
    if (t < 64) {
        // reference: inv_freq = 1.0f32 / (10000 ** (i/64) computed in f32)
        double x = (double)t / 64.0;
        double p = exp(x * 9.210340371976184);   // ln(10000)
        invf[t] = 1.0f / (float)p;               // f32 reciprocal, like reference
    }
    __syncthreads();
    int pos = blockIdx.x * 4 + (t >> 6);
    int i = t & 63;
    if (pos < S) {
        float arg = (float)pos * invf[i];        // f32 product, matches reference rounding
        double a = (double)arg;
        double k = rint(a * 0.15915494309189535);   // 1/(2*pi)
        float r = (float)(a - k * 6.283185307179586);
        float s, c;
        __sincosf(r, &s, &c);                    // |r| <= pi: ~4e-7 abs error
        g_cos[pos * 64 + i] = c;
        g_sin[pos * 64 + i] = s;
    }
}

// ---------------- fused QKV projection: [8 x 4096] @ [4096 x 6144] ----------------
// grid: (NCOLS/256, KSPLIT), block 256. K-split partials via atomicAdd.
__global__ void proj_qkv(const float* __restrict__ hid,
                         const float* __restrict__ Wq,
                         const float* __restrict__ Wk,
                         const float* __restrict__ Wv) {
    __shared__ float hs[NROWS][KCH];
    int j = blockIdx.x * 256 + threadIdx.x;
    int k0 = blockIdx.y * KCH;
    for (int idx = threadIdx.x; idx < NROWS * KCH; idx += 256) {
        int r = idx / KCH, k = idx % KCH;
        hs[r][k] = hid[r * DMODEL + k0 + k];
    }
    __syncthreads();

    const float* W; int ncol; int jj;
    if (j < DMODEL)             { W = Wq; ncol = DMODEL; jj = j; }
    else if (j < DMODEL + 1024) { W = Wk; ncol = 1024;   jj = j - DMODEL; }
    else                        { W = Wv; ncol = 1024;   jj = j - DMODEL - 1024; }

    float acc[NROWS];
#pragma unroll
    for (int r = 0; r < NROWS; r++) acc[r] = 0.f;
    const float* wp = W + (size_t)k0 * ncol + jj;
#pragma unroll 4
    for (int k = 0; k < KCH; k++) {
        float w = wp[(size_t)k * ncol];
#pragma unroll
        for (int r = 0; r < NROWS; r++) acc[r] += hs[r][k] * w;
    }
#pragma unroll
    for (int r = 0; r < NROWS; r++) atomicAdd(&g_qkv[r * NCOLS + j], acc[r]);
}

// ---------------- rope new q/k, copy v ----------------
__global__ void rope_qkv(int S) {
    int idx = blockIdx.x * 256 + threadIdx.x;
    if (idx >= NB * NH * NQ * HD) return;
    int d = idx & 127;
    int q = (idx >> 7) & 3;
    int h = (idx >> 9) & 31;
    int b = idx >> 14;
    int pos = S - NQ + q;
    int row = b * NQ + q;
    float c = g_cos[pos * 64 + (d & 63)];
    float s = g_sin[pos * 64 + (d & 63)];
    {
        float x  = g_qkv[row * NCOLS + h * HD + d];
        float xo = g_qkv[row * NCOLS + h * HD + (d ^ 64)];
        float rot = (d < 64) ? -xo : xo;
        g_qr[((b * NH + h) * NQ + q) * HD + d] = x * c + rot * s;
    }
    if (h < NHK) {
        float x  = g_qkv[row * NCOLS + DMODEL + h * HD + d];
        float xo = g_qkv[row * NCOLS + DMODEL + h * HD + (d ^ 64)];
        float rot = (d < 64) ? -xo : xo;
        g_knew[((b * NHK + h) * NQ + q) * HD + d] = x * c + rot * s;
        g_vnew[((b * NHK + h) * NQ + q) * HD + d] =
            g_qkv[row * NCOLS + DMODEL + 1024 + h * HD + d];
    }
}

// ---------------- draft scores: warp per (b,h,s); rope k on the fly ----------------
// grid: (ceil(S/8), NB*NH), block 256 (8 warps)
__global__ void draft_kernel(const float* __restrict__ kcache, int S, int KV) {
    __shared__ float qs[NQ * HD];
    int bh = blockIdx.y;
    int b = bh >> 5, h = bh & 31;
    for (int i = threadIdx.x; i < NQ * HD; i += 256)
        qs[i] = g_qr[(size_t)bh * NQ * HD + i];
    __syncthreads();

    int warp = threadIdx.x >> 5, lane = threadIdx.x & 31;
    int s = blockIdx.x * 8 + warp;
    if (s >= S) return;

    float4 kr;
    if (s < KV) {
        float4 x = *(const float4*)&kcache[((size_t)bh * KV + s) * HD + lane * 4];
        float4 cv = *(const float4*)&g_cos[s * 64 + (lane & 15) * 4];
        float4 sv = *(const float4*)&g_sin[s * 64 + (lane & 15) * 4];
        float sign = (lane < 16) ? -1.f : 1.f;
        float ox = __shfl_xor_sync(0xffffffffu, x.x, 16);
        float oy = __shfl_xor_sync(0xffffffffu, x.y, 16);
        float oz = __shfl_xor_sync(0xffffffffu, x.z, 16);
        float ow = __shfl_xor_sync(0xffffffffu, x.w, 16);
        kr.x = x.x * cv.x + sign * ox * sv.x;
        kr.y = x.y * cv.y + sign * oy * sv.y;
        kr.z = x.z * cv.z + sign * oz * sv.z;
        kr.w = x.w * cv.w + sign * ow * sv.w;
    } else {
        int hk = h >> 2;
        int qq = s - KV;
        kr = *(const float4*)&g_knew[(((b * NHK + hk) * NQ) + qq) * HD + lane * 4];
    }

#pragma unroll
    for (int qq = 0; qq < NQ; qq++) {
        const float* qp = &qs[qq * HD + lane * 4];
        float p = kr.x * qp[0] + kr.y * qp[1] + kr.z * qp[2] + kr.w * qp[3];
        p += __shfl_xor_sync(0xffffffffu, p, 16);
        p += __shfl_xor_sync(0xffffffffu, p, 8);
        p += __shfl_xor_sync(0xffffffffu, p, 4);
        p += __shfl_xor_sync(0xffffffffu, p, 2);
        p += __shfl_xor_sync(0xffffffffu, p, 1);
        if (lane == 0) g_draft[(size_t)(bh * NQ + qq) * S + s] = p;
    }
}

// ---------------- per-row top-k threshold via binary search on sortable keys ----------------
__global__ void topk_thresh(int S, int nrem) {
    __shared__ unsigned int keys[SMAX];
    __shared__ float wmax[8];
    __shared__ int scnt;
    int row = blockIdx.x;
    const float* dr = &g_draft[(size_t)row * S];
    int lane = threadIdx.x & 31, warp = threadIdx.x >> 5;

    float mx = -3.4e38f;
    for (int i = threadIdx.x; i < S; i += 256) {
        float v = dr[i];
        mx = fmaxf(mx, v);
        unsigned int u = __float_as_uint(v);
        keys[i] = (u & 0x80000000u) ? ~u : (u | 0x80000000u);
    }
#pragma unroll
    for (int o = 16; o; o >>= 1) mx = fmaxf(mx, __shfl_xor_sync(0xffffffffu, mx, o));
    if (lane == 0) wmax[warp] = mx;
    __syncthreads();
    if (threadIdx.x == 0) {
        float m = wmax[0];
#pragma unroll
        for (int w = 1; w < 8; w++) m = fmaxf(m, wmax[w]);
        g_rowmax[row] = m;
    }

    unsigned int lo = 0u, hi = 0xFFFFFFFFu;
    for (int it = 0; it < 33; it++) {
        if (lo >= hi) break;
        unsigned int mid = lo + ((hi - lo) >> 1) + 1u;
        __syncthreads();
        if (threadIdx.x == 0) scnt = 0;
        __syncthreads();
        int c = 0;
        for (int i = threadIdx.x; i < S; i += 256) c += (keys[i] >= mid);
#pragma unroll
        for (int o = 16; o; o >>= 1) c += __shfl_xor_sync(0xffffffffu, c, o);
        if (lane == 0) atomicAdd(&scnt, c);
        __syncthreads();
        int tot = scnt;
        if (tot >= nrem) lo = mid; else hi = mid - 1u;
    }
    if (threadIdx.x == 0) g_thrkey[row] = lo;
}

// ---------------- sparse softmax * V gather ----------------
// grid: (NROWS_ATT, VSPLIT), block 128 (thread t owns dim d = t)
__global__ void attn_gather(const float* __restrict__ vcache, int S, int KV) {
    __shared__ int sidx[512];
    __shared__ float sw[512];
    __shared__ int cnt;
    __shared__ float wden[4];
    int row = blockIdx.x;
    int bh = row >> 2;
    int b = bh >> 5, h = bh & 31;
    int chunk = (S + VSPLIT - 1) / VSPLIT;
    int s0 = blockIdx.y * chunk;
    int s1 = min(S, s0 + chunk);
    int t = threadIdx.x;
    if (t == 0) cnt = 0;
    __syncthreads();

    unsigned int thr = g_thrkey[row];
    float mx = g_rowmax[row];
    const float* dr = &g_draft[(size_t)row * S];
    for (int s = s0 + t; s < s1; s += 128) {
        float v = dr[s];
        unsigned int u = __float_as_uint(v);
        unsigned int key = (u & 0x80000000u) ? ~u : (u | 0x80000000u);
        if (key >= thr) {
            int p = atomicAdd(&cnt, 1);
            sidx[p] = s;
            sw[p] = __expf((v - mx) * 0.08838834764831843f);  // 1/sqrt(128)
        }
    }
    __syncthreads();
    int n = cnt;
    int hk = h >> 2;
    float acc = 0.f;
#pragma unroll 4
    for (int i = 0; i < n; i++) {
        int s = sidx[i];
        float w = sw[i];
        const float* vp = (s < KV)
            ? &vcache[((size_t)bh * KV + s) * HD]
            : &g_vnew[(((b * NHK + hk) * NQ) + (s - KV)) * HD];
        acc += w * vp[t];
    }
    atomicAdd(&g_num[row * HD + t], acc);

    float dsum = 0.f;
    for (int i = t; i < n; i += 128) dsum += sw[i];
#pragma unroll
    for (int o = 16; o; o >>= 1) dsum += __shfl_xor_sync(0xffffffffu, dsum, o);
    if ((t & 31) == 0) wden[t >> 5] = dsum;
    __syncthreads();
    if (t == 0) atomicAdd(&g_den[row], wden[0] + wden[1] + wden[2] + wden[3]);
}

// ---------------- finalize: divide + transpose heads ----------------
__global__ void finalize_attn() {
    int idx = blockIdx.x * 256 + threadIdx.x;
    if (idx >= NROWS_ATT * HD) return;
    int d = idx & 127;
    int row = idx >> 7;
    int q = row & 3, h = (row >> 2) & 31, b = row >> 7;
    float val = g_num[row * HD + d] / g_den[row];
    g_attn[(b * NQ + q) * DMODEL + h * HD + d] = val;
}

// ---------------- output projection: [8 x 4096] @ Wo[4096 x 4096] ----------------
__global__ void proj_out(const float* __restrict__ Wo, float* __restrict__ out) {
    __shared__ float hs[NROWS][KCH];
    int j = blockIdx.x * 256 + threadIdx.x;
    int k0 = blockIdx.y * KCH;
    for (int idx = threadIdx.x; idx < NROWS * KCH; idx += 256) {
        int r = idx / KCH, k = idx % KCH;
        hs[r][k] = g_attn[r * DMODEL + k0 + k];
    }
    __syncthreads();
    float acc[NROWS];
#pragma unroll
    for (int r = 0; r < NROWS; r++) acc[r] = 0.f;
    const float* wp = Wo + (size_t)k0 * DMODEL + j;
#pragma unroll 4
    for (int k = 0; k < KCH; k++) {
        float w = wp[(size_t)k * DMODEL];
#pragma unroll
        for (int r = 0; r < NROWS; r++) acc[r] += hs[r][k] * w;
    }
#pragma unroll
    for (int r = 0; r < NROWS; r++) atomicAdd(&out[r * DMODEL + j], acc[r]);
}

// ---------------- launcher ----------------
extern "C" void kernel_launch(void* const* d_in, const int* in_sizes, int n_in,
                              void* d_out, int out_size) {
    const float* hid    = (const float*)d_in[0];
    const float* kcache = (const float*)d_in[1];
    const float* vcache = (const float*)d_in[2];
    const float* Wq     = (const float*)d_in[3];
    const float* Wk     = (const float*)d_in[4];
    const float* Wv     = (const float*)d_in[5];
    const float* Wo     = (const float*)d_in[6];
    float* out = (float*)d_out;

    int KV = in_sizes[1] / (NB * NH * HD);
    int S = KV + NQ;
    if (S > SMAX) S = SMAX;  // safety clamp (expected S=4100)
    int mo = S - (int)((double)S * 0.9);
    int cap = (S < 128) ? S : 128;
    int nrem = (cap > mo) ? cap : mo;
    if (nrem > 500) nrem = 500;  // shared-list safety (expected 410)

    int zmax = NROWS * NCOLS;  // largest buffer to zero (49152)
    if (out_size > zmax) zmax = out_size;
    zero_bufs<<<(zmax + 255) / 256, 256>>>(out, out_size);
    rope_table<<<(S + 3) / 4, 256>>>(S);
    proj_qkv<<<dim3(NCOLS / 256, KSPLIT), 256>>>(hid, Wq, Wk, Wv);
    rope_qkv<<<(NB * NH * NQ * HD + 255) / 256, 256>>>(S);
    draft_kernel<<<dim3((S + 7) / 8, NB * NH), 256>>>(kcache, S, KV);
    topk_thresh<<<NROWS_ATT, 256>>>(S, nrem);
    attn_gather<<<dim3(NROWS_ATT, VSPLIT), 128>>>(vcache, S, KV);
    finalize_attn<<<(NROWS_ATT * HD + 255) / 256, 256>>>();
    proj_out<<<dim3(DMODEL / 256, KSPLIT), 256>>>(Wo, out);
}

// round 4
// speedup vs baseline: 1.2562x; 1.2562x over previous
#include <cuda_runtime.h>
#include <math.h>

#define NB 2
#define NQ 4
#define NH 32
#define NHK 8
#define HD 128
#define DMODEL 4096
#define NCOLS (DMODEL + 1024 + 1024)   // 6144 fused qkv output columns
#define NROWS (NB * NQ)                // 8
#define SMAX 4352
#define NROWS_ATT (NB * NH * NQ)       // 256
#define KSPLIT 16
#define KCH (DMODEL / KSPLIT)          // 256
#define VSPLIT 8
#define TS 64                          // draft tile: key rows per block
#define KPAD 132                       // padded K-tile row (conflict-free)

// ---------------- scratch (device globals; no allocation) ----------------
__device__ float g_qkv[NROWS * NCOLS];
__device__ float g_cos[SMAX * 64];
__device__ float g_sin[SMAX * 64];
__device__ float g_qr[NB * NH * NQ * HD];
__device__ float g_knew[NB * NHK * NQ * HD];
__device__ float g_vnew[NB * NHK * NQ * HD];
__device__ float g_draft[NROWS_ATT * SMAX];
__device__ unsigned int g_thrkey[NROWS_ATT];
__device__ float g_rowmax[NROWS_ATT];
__device__ float g_num[NROWS_ATT * HD];
__device__ float g_den[NROWS_ATT];

// ---------------- init: zero accumulators + rope tables in one kernel ----------------
__global__ void init_kernel(float* __restrict__ out, int osz, int zb, int S) {
    if ((int)blockIdx.x < zb) {
        int i = blockIdx.x * 256 + threadIdx.x;
        if (i < NROWS * NCOLS)   g_qkv[i] = 0.f;
        if (i < NROWS_ATT * HD)  g_num[i] = 0.f;
        if (i < NROWS_ATT)       g_den[i] = 0.f;
        if (i < osz)             out[i]  = 0.f;
        return;
    }
    __shared__ float invf[64];
    int t = threadIdx.x;
    if (t < 64) {
        double x = (double)t / 64.0;
        double p = exp(x * 9.210340371976184);   // ln(10000)
        invf[t] = 1.0f / (float)p;
    }
    __syncthreads();
    int pos = (blockIdx.x - zb) * 4 + (t >> 6);
    int i = t & 63;
    if (pos < S) {
        float arg = (float)pos * invf[i];
        double a = (double)arg;
        double k = rint(a * 0.15915494309189535);
        float r = (float)(a - k * 6.283185307179586);
        float s, c;
        __sincosf(r, &s, &c);
        g_cos[pos * 64 + i] = c;
        g_sin[pos * 64 + i] = s;
    }
}

// ---------------- fused QKV projection: 4 cols/thread, float4 streams ----------------
// grid: (NCOLS/1024, KSPLIT), block 256
__global__ void __launch_bounds__(256) proj_qkv(const float* __restrict__ hid,
                                                const float* __restrict__ Wq,
                                                const float* __restrict__ Wk,
                                                const float* __restrict__ Wv) {
    __shared__ float hs[NROWS][KCH];
    int t = threadIdx.x;
    int j = (blockIdx.x * 256 + t) * 4;
    int k0 = blockIdx.y * KCH;
    // load hidden slice (float4)
    for (int idx = t; idx < NROWS * KCH / 4; idx += 256) {
        int r = idx / (KCH / 4), c4 = idx % (KCH / 4);
        *(float4*)&hs[r][c4 * 4] = *(const float4*)&hid[r * DMODEL + k0 + c4 * 4];
    }
    __syncthreads();

    const float* W; int ncol; int jj;
    if (j < DMODEL)             { W = Wq; ncol = DMODEL; jj = j; }
    else if (j < DMODEL + 1024) { W = Wk; ncol = 1024;   jj = j - DMODEL; }
    else                        { W = Wv; ncol = 1024;   jj = j - DMODEL - 1024; }

    float4 acc[NROWS];
#pragma unroll
    for (int r = 0; r < NROWS; r++) acc[r] = make_float4(0.f, 0.f, 0.f, 0.f);
    const float* wp = W + (size_t)k0 * ncol + jj;
#pragma unroll 4
    for (int k = 0; k < KCH; k++) {
        float4 w4 = *(const float4*)(wp + (size_t)k * ncol);
#pragma unroll
        for (int r = 0; r < NROWS; r++) {
            float h = hs[r][k];
            acc[r].x += h * w4.x; acc[r].y += h * w4.y;
            acc[r].z += h * w4.z; acc[r].w += h * w4.w;
        }
    }
#pragma unroll
    for (int r = 0; r < NROWS; r++) {
        float* o = &g_qkv[r * NCOLS + j];
        atomicAdd(o + 0, acc[r].x); atomicAdd(o + 1, acc[r].y);
        atomicAdd(o + 2, acc[r].z); atomicAdd(o + 3, acc[r].w);
    }
}

// ---------------- rope new q/k, copy v (float4 pair tasks) ----------------
// tasks = NB*NH*NQ*16 = 4096 -> 16 blocks x 256
__global__ void rope_qkv(int S) {
    int idx = blockIdx.x * 256 + threadIdx.x;
    int c = (idx & 15) * 4;
    int q = (idx >> 4) & 3;
    int h = (idx >> 6) & 31;
    int b = idx >> 11;
    int pos = S - NQ + q;
    int row = b * NQ + q;
    float4 cv = *(const float4*)&g_cos[pos * 64 + c];
    float4 sv = *(const float4*)&g_sin[pos * 64 + c];
    const float* base = g_qkv + row * NCOLS;
    {
        float4 xl = *(const float4*)(base + h * HD + c);
        float4 xh = *(const float4*)(base + h * HD + c + 64);
        float4 lo, hi;
        lo.x = xl.x * cv.x - xh.x * sv.x;  hi.x = xh.x * cv.x + xl.x * sv.x;
        lo.y = xl.y * cv.y - xh.y * sv.y;  hi.y = xh.y * cv.y + xl.y * sv.y;
        lo.z = xl.z * cv.z - xh.z * sv.z;  hi.z = xh.z * cv.z + xl.z * sv.z;
        lo.w = xl.w * cv.w - xh.w * sv.w;  hi.w = xh.w * cv.w + xl.w * sv.w;
        float* qo = g_qr + ((b * NH + h) * NQ + q) * HD;
        *(float4*)(qo + c) = lo; *(float4*)(qo + c + 64) = hi;
    }
    if (h < NHK) {
        const float* kb = base + DMODEL + h * HD;
        float4 xl = *(const float4*)(kb + c);
        float4 xh = *(const float4*)(kb + c + 64);
        float4 lo, hi;
        lo.x = xl.x * cv.x - xh.x * sv.x;  hi.x = xh.x * cv.x + xl.x * sv.x;
        lo.y = xl.y * cv.y - xh.y * sv.y;  hi.y = xh.y * cv.y + xl.y * sv.y;
        lo.z = xl.z * cv.z - xh.z * sv.z;  hi.z = xh.z * cv.z + xl.z * sv.z;
        lo.w = xl.w * cv.w - xh.w * sv.w;  hi.w = xh.w * cv.w + xl.w * sv.w;
        float* ko = g_knew + ((b * NHK + h) * NQ + q) * HD;
        *(float4*)(ko + c) = lo; *(float4*)(ko + c + 64) = hi;
        const float* vb = base + DMODEL + 1024 + h * HD;
        float* vo = g_vnew + ((b * NHK + h) * NQ + q) * HD;
        *(float4*)(vo + c)      = *(const float4*)(vb + c);
        *(float4*)(vo + c + 64) = *(const float4*)(vb + c + 64);
    }
}

// ---------------- draft scores: tiled, rope-on-load ----------------
// grid: (ceil(S/TS), NB*NH), block 256
__global__ void __launch_bounds__(256) draft_kernel(const float* __restrict__ kcache,
                                                    int S, int KV) {
    __shared__ float ks[TS][KPAD];
    __shared__ float qsf[NQ * HD];
    int bh = blockIdx.y;
    int b = bh >> 5, h = bh & 31;
    int s0 = blockIdx.x * TS;
    int t = threadIdx.x;

    if (t < 128)
        *(float4*)&qsf[t * 4] = *(const float4*)&g_qr[(size_t)bh * NQ * HD + t * 4];

    // load + rope K tile: 1024 float4-pair tasks
    for (int task = t; task < TS * 16; task += 256) {
        int r = task >> 4, c = (task & 15) * 4;
        int s = s0 + r;
        if (s >= S) continue;
        float4 lo, hi;
        if (s < KV) {
            const float* kp = kcache + ((size_t)bh * KV + s) * HD;
            float4 xl = *(const float4*)(kp + c);
            float4 xh = *(const float4*)(kp + c + 64);
            float4 cv = *(const float4*)&g_cos[s * 64 + c];
            float4 sv = *(const float4*)&g_sin[s * 64 + c];
            lo.x = xl.x * cv.x - xh.x * sv.x;  hi.x = xh.x * cv.x + xl.x * sv.x;
            lo.y = xl.y * cv.y - xh.y * sv.y;  hi.y = xh.y * cv.y + xl.y * sv.y;
            lo.z = xl.z * cv.z - xh.z * sv.z;  hi.z = xh.z * cv.z + xl.z * sv.z;
            lo.w = xl.w * cv.w - xh.w * sv.w;  hi.w = xh.w * cv.w + xl.w * sv.w;
        } else {
            const float* kp = g_knew + (((b * NHK + (h >> 2)) * NQ) + (s - KV)) * HD;
            lo = *(const float4*)(kp + c);
            hi = *(const float4*)(kp + c + 64);
        }
        *(float4*)&ks[r][c] = lo;
        *(float4*)&ks[r][c + 64] = hi;
    }
    __syncthreads();

    int q = t >> 6, sl = t & 63;
    int s = s0 + sl;
    if (s < S) {
        const float* kr = ks[sl];
        const float* qr = &qsf[q * HD];
        float a0 = 0.f, a1 = 0.f;
#pragma unroll
        for (int k = 0; k < HD; k += 8) {
            float4 k0v = *(const float4*)(kr + k);
            float4 q0v = *(const float4*)(qr + k);
            float4 k1v = *(const float4*)(kr + k + 4);
            float4 q1v = *(const float4*)(qr + k + 4);
            a0 += k0v.x * q0v.x + k0v.y * q0v.y + k0v.z * q0v.z + k0v.w * q0v.w;
            a1 += k1v.x * q1v.x + k1v.y * q1v.y + k1v.z * q1v.z + k1v.w * q1v.w;
        }
        g_draft[(size_t)(bh * NQ + q) * S + s] = a0 + a1;
    }
}

// ---------------- per-row top-k threshold: 4-level radix select ----------------
__global__ void __launch_bounds__(256) topk_thresh(int S, int nrem) {
    __shared__ unsigned int keys[SMAX];
    __shared__ int hist[256];
    __shared__ float wmax[8];
    __shared__ unsigned int s_prefix;
    __shared__ int s_need;
    int row = blockIdx.x;
    const float* dr = &g_draft[(size_t)row * S];
    int t = threadIdx.x, lane = t & 31, warp = t >> 5;

    float mx = -3.4e38f;
    for (int i = t; i < S; i += 256) {
        float v = dr[i];
        mx = fmaxf(mx, v);
        unsigned int u = __float_as_uint(v);
        keys[i] = (u & 0x80000000u) ? ~u : (u | 0x80000000u);
    }
#pragma unroll
    for (int o = 16; o; o >>= 1) mx = fmaxf(mx, __shfl_xor_sync(0xffffffffu, mx, o));
    if (lane == 0) wmax[warp] = mx;
    __syncthreads();
    if (t == 0) {
        float m = wmax[0];
#pragma unroll
        for (int w = 1; w < 8; w++) m = fmaxf(m, wmax[w]);
        g_rowmax[row] = m;
    }

    unsigned int prefix = 0u;
    int need = nrem;
    for (int level = 3; level >= 0; level--) {
        hist[t] = 0;
        __syncthreads();
        int shift = level * 8;
        unsigned int pmask = (level == 3) ? 0u : (0xFFFFFFFFu << (shift + 8));
        for (int i = t; i < S; i += 256) {
            unsigned int k = keys[i];
            if ((k & pmask) == prefix) atomicAdd(&hist[(k >> shift) & 255], 1);
        }
        __syncthreads();
        if (t == 0) {
            int cum = 0, d = 255;
            for (; d > 0; d--) { cum += hist[d]; if (cum >= need) break; }
            if (cum < need) { cum += hist[0]; d = 0; }
            s_need = need - (cum - hist[d]);
            s_prefix = prefix | ((unsigned int)d << shift);
        }
        __syncthreads();
        prefix = s_prefix; need = s_need;
        __syncthreads();
    }
    if (t == 0) g_thrkey[row] = prefix;
}

// ---------------- sparse softmax * V gather ----------------
// grid: (NROWS_ATT, VSPLIT), block 256: 2 i-groups x 128 dims
__global__ void __launch_bounds__(256) attn_gather(const float* __restrict__ vcache,
                                                   int S, int KV) {
    __shared__ int sidx[512];
    __shared__ float sw[512];
    __shared__ int cnt;
    __shared__ float accbuf[HD];
    __shared__ float wden[8];
    int row = blockIdx.x;
    int bh = row >> 2;
    int b = bh >> 5, h = bh & 31;
    int chunk = (S + VSPLIT - 1) / VSPLIT;
    int s0 = blockIdx.y * chunk;
    int s1 = min(S, s0 + chunk);
    int t = threadIdx.x;
    if (t == 0) cnt = 0;
    __syncthreads();

    unsigned int thr = g_thrkey[row];
    float mx = g_rowmax[row];
    const float* dr = &g_draft[(size_t)row * S];
    for (int s = s0 + t; s < s1; s += 256) {
        float v = dr[s];
        unsigned int u = __float_as_uint(v);
        unsigned int key = (u & 0x80000000u) ? ~u : (u | 0x80000000u);
        if (key >= thr) {
            int p = atomicAdd(&cnt, 1);
            if (p < 512) {
                sidx[p] = s;
                sw[p] = __expf((v - mx) * 0.08838834764831843f);  // 1/sqrt(128)
            }
        }
    }
    __syncthreads();
    int n = min(cnt, 512);
    int hk = h >> 2;
    int g = t >> 7, d = t & 127;
    float acc = 0.f;
#pragma unroll 4
    for (int i = g; i < n; i += 2) {
        int s = sidx[i];
        float w = sw[i];
        const float* vp = (s < KV)
            ? &vcache[((size_t)bh * KV + s) * HD]
            : &g_vnew[(((b * NHK + hk) * NQ) + (s - KV)) * HD];
        acc += w * vp[d];
    }
    if (g == 1) accbuf[d] = acc;
    __syncthreads();
    if (g == 0) atomicAdd(&g_num[row * HD + d], acc + accbuf[d]);

    float dsum = 0.f;
    for (int i = t; i < n; i += 256) dsum += sw[i];
#pragma unroll
    for (int o = 16; o; o >>= 1) dsum += __shfl_xor_sync(0xffffffffu, dsum, o);
    if ((t & 31) == 0) wden[t >> 5] = dsum;
    __syncthreads();
    if (t == 0) {
        float s8 = 0.f;
#pragma unroll
        for (int w = 0; w < 8; w++) s8 += wden[w];
        atomicAdd(&g_den[row], s8);
    }
}

// ---------------- output projection (finalize fused into tile load) ----------------
// grid: (DMODEL/1024, KSPLIT), block 256, 4 cols/thread
__global__ void __launch_bounds__(256) proj_out(const float* __restrict__ Wo,
                                                float* __restrict__ out) {
    __shared__ float hs[NROWS][KCH];
    int t = threadIdx.x;
    int j = (blockIdx.x * 256 + t) * 4;
    int k0 = blockIdx.y * KCH;
    // load attention output slice with divide + head transpose fused
    for (int idx = t; idx < NROWS * KCH / 4; idx += 256) {
        int r = idx / (KCH / 4);            // r = b*NQ + q
        int kg = k0 + (idx % (KCH / 4)) * 4;
        int b = r >> 2, q = r & 3;
        int h = kg >> 7, d = kg & 127;
        int row2 = ((b * NH + h) * NQ + q);
        float4 v = *(const float4*)&g_num[row2 * HD + d];
        float inv = 1.0f / g_den[row2];
        v.x *= inv; v.y *= inv; v.z *= inv; v.w *= inv;
        *(float4*)&hs[r][kg - k0] = v;
    }
    __syncthreads();

    float4 acc[NROWS];
#pragma unroll
    for (int r = 0; r < NROWS; r++) acc[r] = make_float4(0.f, 0.f, 0.f, 0.f);
    const float* wp = Wo + (size_t)k0 * DMODEL + j;
#pragma unroll 4
    for (int k = 0; k < KCH; k++) {
        float4 w4 = *(const float4*)(wp + (size_t)k * DMODEL);
#pragma unroll
        for (int r = 0; r < NROWS; r++) {
            float h = hs[r][k];
            acc[r].x += h * w4.x; acc[r].y += h * w4.y;
            acc[r].z += h * w4.z; acc[r].w += h * w4.w;
        }
    }
#pragma unroll
    for (int r = 0; r < NROWS; r++) {
        float* o = &out[r * DMODEL + j];
        atomicAdd(o + 0, acc[r].x); atomicAdd(o + 1, acc[r].y);
        atomicAdd(o + 2, acc[r].z); atomicAdd(o + 3, acc[r].w);
    }
}

// ---------------- launcher ----------------
extern "C" void kernel_launch(void* const* d_in, const int* in_sizes, int n_in,
                              void* d_out, int out_size) {
    const float* hid    = (const float*)d_in[0];
    const float* kcache = (const float*)d_in[1];
    const float* vcache = (const float*)d_in[2];
    const float* Wq     = (const float*)d_in[3];
    const float* Wk     = (const float*)d_in[4];
    const float* Wv     = (const float*)d_in[5];
    const float* Wo     = (const float*)d_in[6];
    float* out = (float*)d_out;

    int KV = in_sizes[1] / (NB * NH * HD);
    int S = KV + NQ;
    if (S > SMAX) S = SMAX;
    int mo = S - (int)((double)S * 0.9);
    int cap = (S < 128) ? S : 128;
    int nrem = (cap > mo) ? cap : mo;
    if (nrem > 500) nrem = 500;

    int zmax = NROWS * NCOLS;
    if (out_size > zmax) zmax = out_size;
    int zb = (zmax + 255) / 256;
    int rb = (S + 3) / 4;
    init_kernel<<<zb + rb, 256>>>(out, out_size, zb, S);
    proj_qkv<<<dim3(NCOLS / 1024, KSPLIT), 256>>>(hid, Wq, Wk, Wv);
    rope_qkv<<<16, 256>>>(S);
    draft_kernel<<<dim3((S + TS - 1) / TS, NB * NH), 256>>>(kcache, S, KV);
    topk_thresh<<<NROWS_ATT, 256>>>(S, nrem);
    attn_gather<<<dim3(NROWS_ATT, VSPLIT), 256>>>(vcache, S, KV);
    proj_out<<<dim3(DMODEL / 1024, KSPLIT), 256>>>(Wo, out);
}

// round 5
// speedup vs baseline: 1.4639x; 1.1654x over previous
#include <cuda_runtime.h>
#include <math.h>

#define NB 2
#define NQ 4
#define NH 32
#define NHK 8
#define HD 128
#define DMODEL 4096
#define NCOLS (DMODEL + 1024 + 1024)   // 6144 fused qkv output columns
#define NROWS (NB * NQ)                // 8
#define SMAX 4352
#define NROWS_ATT (NB * NH * NQ)       // 256
#define KSPLIT 64
#define KCH (DMODEL / KSPLIT)          // 64
#define VSPLIT 8
#define TS 64                          // draft tile: key rows per block
#define KPAD 132                       // padded K-tile row (33 float4s, odd -> conflict-free)

// ---------------- scratch (device globals; no allocation) ----------------
__device__ float g_qkv[NROWS * NCOLS];
__device__ float g_cos[SMAX * 64];
__device__ float g_sin[SMAX * 64];
__device__ float g_qr[NB * NH * NQ * HD];
__device__ float g_knew[NB * NHK * NQ * HD];
__device__ float g_vnew[NB * NHK * NQ * HD];
__device__ float g_draft[NROWS_ATT * SMAX];
__device__ unsigned int g_thrkey[NROWS_ATT];
__device__ float g_rowmax[NROWS_ATT];
__device__ float g_num[NROWS_ATT * HD];
__device__ float g_den[NROWS_ATT];

// ---------------- init: zero accumulators + rope tables in one kernel ----------------
__global__ void init_kernel(float* __restrict__ out, int osz, int zb, int S) {
    if ((int)blockIdx.x < zb) {
        int i = blockIdx.x * 256 + threadIdx.x;
        if (i < NROWS * NCOLS)   g_qkv[i] = 0.f;
        if (i < NROWS_ATT * HD)  g_num[i] = 0.f;
        if (i < NROWS_ATT)       g_den[i] = 0.f;
        if (i < osz)             out[i]  = 0.f;
        return;
    }
    __shared__ float invf[64];
    int t = threadIdx.x;
    if (t < 64) {
        double x = (double)t / 64.0;
        double p = exp(x * 9.210340371976184);   // ln(10000)
        invf[t] = 1.0f / (float)p;
    }
    __syncthreads();
    int pos = (blockIdx.x - zb) * 4 + (t >> 6);
    int i = t & 63;
    if (pos < S) {
        float arg = (float)pos * invf[i];
        double a = (double)arg;
        double k = rint(a * 0.15915494309189535);
        float r = (float)(a - k * 6.283185307179586);
        float s, c;
        __sincosf(r, &s, &c);
        g_cos[pos * 64 + i] = c;
        g_sin[pos * 64 + i] = s;
    }
}

// ---------------- fused QKV projection: 4 cols/thread, KSPLIT=64 ----------------
// grid: (NCOLS/1024, KSPLIT), block 256
__global__ void __launch_bounds__(256) proj_qkv(const float* __restrict__ hid,
                                                const float* __restrict__ Wq,
                                                const float* __restrict__ Wk,
                                                const float* __restrict__ Wv) {
    __shared__ float hs[NROWS][KCH];
    int t = threadIdx.x;
    int j = (blockIdx.x * 256 + t) * 4;
    int k0 = blockIdx.y * KCH;
    // load hidden slice (float4): 8*64/4 = 128 tasks
    if (t < NROWS * KCH / 4) {
        int r = t / (KCH / 4), c4 = t % (KCH / 4);
        *(float4*)&hs[r][c4 * 4] = *(const float4*)&hid[r * DMODEL + k0 + c4 * 4];
    }
    __syncthreads();

    const float* W; int ncol; int jj;
    if (j < DMODEL)             { W = Wq; ncol = DMODEL; jj = j; }
    else if (j < DMODEL + 1024) { W = Wk; ncol = 1024;   jj = j - DMODEL; }
    else                        { W = Wv; ncol = 1024;   jj = j - DMODEL - 1024; }

    float4 acc[NROWS];
#pragma unroll
    for (int r = 0; r < NROWS; r++) acc[r] = make_float4(0.f, 0.f, 0.f, 0.f);
    const float* wp = W + (size_t)k0 * ncol + jj;
#pragma unroll 8
    for (int k = 0; k < KCH; k++) {
        float4 w4 = *(const float4*)(wp + (size_t)k * ncol);
#pragma unroll
        for (int r = 0; r < NROWS; r++) {
            float h = hs[r][k];
            acc[r].x += h * w4.x; acc[r].y += h * w4.y;
            acc[r].z += h * w4.z; acc[r].w += h * w4.w;
        }
    }
#pragma unroll
    for (int r = 0; r < NROWS; r++) {
        float* o = &g_qkv[r * NCOLS + j];
        atomicAdd(o + 0, acc[r].x); atomicAdd(o + 1, acc[r].y);
        atomicAdd(o + 2, acc[r].z); atomicAdd(o + 3, acc[r].w);
    }
}

// ---------------- rope new q/k, copy v (float4 pair tasks) ----------------
// tasks = NB*NH*NQ*16 = 4096 -> 16 blocks x 256
__global__ void rope_qkv(int S) {
    int idx = blockIdx.x * 256 + threadIdx.x;
    int c = (idx & 15) * 4;
    int q = (idx >> 4) & 3;
    int h = (idx >> 6) & 31;
    int b = idx >> 11;
    int pos = S - NQ + q;
    int row = b * NQ + q;
    float4 cv = *(const float4*)&g_cos[pos * 64 + c];
    float4 sv = *(const float4*)&g_sin[pos * 64 + c];
    const float* base = g_qkv + row * NCOLS;
    {
        float4 xl = *(const float4*)(base + h * HD + c);
        float4 xh = *(const float4*)(base + h * HD + c + 64);
        float4 lo, hi;
        lo.x = xl.x * cv.x - xh.x * sv.x;  hi.x = xh.x * cv.x + xl.x * sv.x;
        lo.y = xl.y * cv.y - xh.y * sv.y;  hi.y = xh.y * cv.y + xl.y * sv.y;
        lo.z = xl.z * cv.z - xh.z * sv.z;  hi.z = xh.z * cv.z + xl.z * sv.z;
        lo.w = xl.w * cv.w - xh.w * sv.w;  hi.w = xh.w * cv.w + xl.w * sv.w;
        float* qo = g_qr + ((b * NH + h) * NQ + q) * HD;
        *(float4*)(qo + c) = lo; *(float4*)(qo + c + 64) = hi;
    }
    if (h < NHK) {
        const float* kb = base + DMODEL + h * HD;
        float4 xl = *(const float4*)(kb + c);
        float4 xh = *(const float4*)(kb + c + 64);
        float4 lo, hi;
        lo.x = xl.x * cv.x - xh.x * sv.x;  hi.x = xh.x * cv.x + xl.x * sv.x;
        lo.y = xl.y * cv.y - xh.y * sv.y;  hi.y = xh.y * cv.y + xl.y * sv.y;
        lo.z = xl.z * cv.z - xh.z * sv.z;  hi.z = xh.z * cv.z + xl.z * sv.z;
        lo.w = xl.w * cv.w - xh.w * sv.w;  hi.w = xh.w * cv.w + xl.w * sv.w;
        float* ko = g_knew + ((b * NHK + h) * NQ + q) * HD;
        *(float4*)(ko + c) = lo; *(float4*)(ko + c + 64) = hi;
        const float* vb = base + DMODEL + 1024 + h * HD;
        float* vo = g_vnew + ((b * NHK + h) * NQ + q) * HD;
        *(float4*)(vo + c)      = *(const float4*)(vb + c);
        *(float4*)(vo + c + 64) = *(const float4*)(vb + c + 64);
    }
}

// ---------------- draft scores: tiled, rope-on-load, 2 q-dots/thread ----------------
// grid: (ceil(S/TS), NB*NH), block 128
__global__ void __launch_bounds__(128) draft_kernel(const float* __restrict__ kcache,
                                                    int S, int KV) {
    __shared__ float ks[TS][KPAD];
    __shared__ float qsf[NQ * HD];
    int bh = blockIdx.y;
    int b = bh >> 5, h = bh & 31;
    int s0 = blockIdx.x * TS;
    int t = threadIdx.x;

    *(float4*)&qsf[t * 4] = *(const float4*)&g_qr[(size_t)bh * NQ * HD + t * 4];

    // load + rope K tile: 1024 float4-pair tasks over 128 threads
    for (int task = t; task < TS * 16; task += 128) {
        int r = task >> 4, c = (task & 15) * 4;
        int s = s0 + r;
        if (s >= S) continue;
        float4 lo, hi;
        if (s < KV) {
            const float* kp = kcache + ((size_t)bh * KV + s) * HD;
            float4 xl = *(const float4*)(kp + c);
            float4 xh = *(const float4*)(kp + c + 64);
            float4 cv = *(const float4*)&g_cos[s * 64 + c];
            float4 sv = *(const float4*)&g_sin[s * 64 + c];
            lo.x = xl.x * cv.x - xh.x * sv.x;  hi.x = xh.x * cv.x + xl.x * sv.x;
            lo.y = xl.y * cv.y - xh.y * sv.y;  hi.y = xh.y * cv.y + xl.y * sv.y;
            lo.z = xl.z * cv.z - xh.z * sv.z;  hi.z = xh.z * cv.z + xl.z * sv.z;
            lo.w = xl.w * cv.w - xh.w * sv.w;  hi.w = xh.w * cv.w + xl.w * sv.w;
        } else {
            const float* kp = g_knew + (((b * NHK + (h >> 2)) * NQ) + (s - KV)) * HD;
            lo = *(const float4*)(kp + c);
            hi = *(const float4*)(kp + c + 64);
        }
        *(float4*)&ks[r][c] = lo;
        *(float4*)&ks[r][c + 64] = hi;
    }
    __syncthreads();

    // compute: thread -> (row sl, q-pair qg); K row read once per 2 dots,
    // q reads are warp-uniform (broadcast)
    int qg = t >> 6, sl = t & 63;
    int s = s0 + sl;
    if (s < S) {
        const float* kr = ks[sl];
        const float* qa = &qsf[(2 * qg) * HD];
        const float* qb = &qsf[(2 * qg + 1) * HD];
        float a0 = 0.f, a1 = 0.f, b0 = 0.f, b1 = 0.f;
#pragma unroll
        for (int k = 0; k < HD; k += 8) {
            float4 k0v = *(const float4*)(kr + k);
            float4 k1v = *(const float4*)(kr + k + 4);
            float4 qa0 = *(const float4*)(qa + k);
            float4 qa1 = *(const float4*)(qa + k + 4);
            float4 qb0 = *(const float4*)(qb + k);
            float4 qb1 = *(const float4*)(qb + k + 4);
            a0 += k0v.x * qa0.x + k0v.y * qa0.y + k0v.z * qa0.z + k0v.w * qa0.w;
            a1 += k1v.x * qa1.x + k1v.y * qa1.y + k1v.z * qa1.z + k1v.w * qa1.w;
            b0 += k0v.x * qb0.x + k0v.y * qb0.y + k0v.z * qb0.z + k0v.w * qb0.w;
            b1 += k1v.x * qb1.x + k1v.y * qb1.y + k1v.z * qb1.z + k1v.w * qb1.w;
        }
        g_draft[(size_t)(bh * NQ + 2 * qg) * S + s]     = a0 + a1;
        g_draft[(size_t)(bh * NQ + 2 * qg + 1) * S + s] = b0 + b1;
    }
}

// ---------------- per-row top-k threshold: 4-level radix select ----------------
__global__ void __launch_bounds__(256) topk_thresh(int S, int nrem) {
    __shared__ unsigned int keys[SMAX];
    __shared__ int hist[256];
    __shared__ float wmax[8];
    __shared__ unsigned int s_prefix;
    __shared__ int s_need;
    int row = blockIdx.x;
    const float* dr = &g_draft[(size_t)row * S];
    int t = threadIdx.x, lane = t & 31, warp = t >> 5;

    float mx = -3.4e38f;
    for (int i = t; i < S; i += 256) {
        float v = dr[i];
        mx = fmaxf(mx, v);
        unsigned int u = __float_as_uint(v);
        keys[i] = (u & 0x80000000u) ? ~u : (u | 0x80000000u);
    }
#pragma unroll
    for (int o = 16; o; o >>= 1) mx = fmaxf(mx, __shfl_xor_sync(0xffffffffu, mx, o));
    if (lane == 0) wmax[warp] = mx;
    __syncthreads();
    if (t == 0) {
        float m = wmax[0];
#pragma unroll
        for (int w = 1; w < 8; w++) m = fmaxf(m, wmax[w]);
        g_rowmax[row] = m;
    }

    unsigned int prefix = 0u;
    int need = nrem;
    for (int level = 3; level >= 0; level--) {
        hist[t] = 0;
        __syncthreads();
        int shift = level * 8;
        unsigned int pmask = (level == 3) ? 0u : (0xFFFFFFFFu << (shift + 8));
        for (int i = t; i < S; i += 256) {
            unsigned int k = keys[i];
            if ((k & pmask) == prefix) atomicAdd(&hist[(k >> shift) & 255], 1);
        }
        __syncthreads();
        if (t == 0) {
            int cum = 0, d = 255;
            for (; d > 0; d--) { cum += hist[d]; if (cum >= need) break; }
            if (cum < need) { cum += hist[0]; d = 0; }
            s_need = need - (cum - hist[d]);
            s_prefix = prefix | ((unsigned int)d << shift);
        }
        __syncthreads();
        prefix = s_prefix; need = s_need;
        __syncthreads();
    }
    if (t == 0) g_thrkey[row] = prefix;
}

// ---------------- sparse softmax * V gather ----------------
// grid: (NROWS_ATT, VSPLIT), block 256: 2 i-groups x 128 dims
__global__ void __launch_bounds__(256) attn_gather(const float* __restrict__ vcache,
                                                   int S, int KV) {
    __shared__ int sidx[512];
    __shared__ float sw[512];
    __shared__ int cnt;
    __shared__ float accbuf[HD];
    __shared__ float wden[8];
    int row = blockIdx.x;
    int bh = row >> 2;
    int b = bh >> 5, h = bh & 31;
    int chunk = (S + VSPLIT - 1) / VSPLIT;
    int s0 = blockIdx.y * chunk;
    int s1 = min(S, s0 + chunk);
    int t = threadIdx.x;
    if (t == 0) cnt = 0;
    __syncthreads();

    unsigned int thr = g_thrkey[row];
    float mx = g_rowmax[row];
    const float* dr = &g_draft[(size_t)row * S];
    for (int s = s0 + t; s < s1; s += 256) {
        float v = dr[s];
        unsigned int u = __float_as_uint(v);
        unsigned int key = (u & 0x80000000u) ? ~u : (u | 0x80000000u);
        if (key >= thr) {
            int p = atomicAdd(&cnt, 1);
            if (p < 512) {
                sidx[p] = s;
                sw[p] = __expf((v - mx) * 0.08838834764831843f);  // 1/sqrt(128)
            }
        }
    }
    __syncthreads();
    int n = min(cnt, 512);
    int hk = h >> 2;
    int g = t >> 7, d = t & 127;
    float acc = 0.f;
#pragma unroll 8
    for (int i = g; i < n; i += 2) {
        int s = sidx[i];
        float w = sw[i];
        const float* vp = (s < KV)
            ? &vcache[((size_t)bh * KV + s) * HD]
            : &g_vnew[(((b * NHK + hk) * NQ) + (s - KV)) * HD];
        acc += w * vp[d];
    }
    if (g == 1) accbuf[d] = acc;
    __syncthreads();
    if (g == 0) atomicAdd(&g_num[row * HD + d], acc + accbuf[d]);

    float dsum = 0.f;
    for (int i = t; i < n; i += 256) dsum += sw[i];
#pragma unroll
    for (int o = 16; o; o >>= 1) dsum += __shfl_xor_sync(0xffffffffu, dsum, o);
    if ((t & 31) == 0) wden[t >> 5] = dsum;
    __syncthreads();
    if (t == 0) {
        float s8 = 0.f;
#pragma unroll
        for (int w = 0; w < 8; w++) s8 += wden[w];
        atomicAdd(&g_den[row], s8);
    }
}

// ---------------- output projection (finalize fused into tile load) ----------------
// grid: (DMODEL/1024, KSPLIT), block 256, 4 cols/thread
__global__ void __launch_bounds__(256) proj_out(const float* __restrict__ Wo,
                                                float* __restrict__ out) {
    __shared__ float hs[NROWS][KCH];
    int t = threadIdx.x;
    int j = (blockIdx.x * 256 + t) * 4;
    int k0 = blockIdx.y * KCH;
    // load attention output slice with divide + head transpose fused (128 tasks)
    if (t < NROWS * KCH / 4) {
        int r = t / (KCH / 4);              // r = b*NQ + q
        int kg = k0 + (t % (KCH / 4)) * 4;
        int b = r >> 2, q = r & 3;
        int h = kg >> 7, d = kg & 127;
        int row2 = ((b * NH + h) * NQ + q);
        float4 v = *(const float4*)&g_num[row2 * HD + d];
        float inv = 1.0f / g_den[row2];
        v.x *= inv; v.y *= inv; v.z *= inv; v.w *= inv;
        *(float4*)&hs[r][kg - k0] = v;
    }
    __syncthreads();

    float4 acc[NROWS];
#pragma unroll
    for (int r = 0; r < NROWS; r++) acc[r] = make_float4(0.f, 0.f, 0.f, 0.f);
    const float* wp = Wo + (size_t)k0 * DMODEL + j;
#pragma unroll 8
    for (int k = 0; k < KCH; k++) {
        float4 w4 = *(const float4*)(wp + (size_t)k * DMODEL);
#pragma unroll
        for (int r = 0; r < NROWS; r++) {
            float h = hs[r][k];
            acc[r].x += h * w4.x; acc[r].y += h * w4.y;
            acc[r].z += h * w4.z; acc[r].w += h * w4.w;
        }
    }
#pragma unroll
    for (int r = 0; r < NROWS; r++) {
        float* o = &out[r * DMODEL + j];
        atomicAdd(o + 0, acc[r].x); atomicAdd(o + 1, acc[r].y);
        atomicAdd(o + 2, acc[r].z); atomicAdd(o + 3, acc[r].w);
    }
}

// ---------------- launcher ----------------
extern "C" void kernel_launch(void* const* d_in, const int* in_sizes, int n_in,
                              void* d_out, int out_size) {
    const float* hid    = (const float*)d_in[0];
    const float* kcache = (const float*)d_in[1];
    const float* vcache = (const float*)d_in[2];
    const float* Wq     = (const float*)d_in[3];
    const float* Wk     = (const float*)d_in[4];
    const float* Wv     = (const float*)d_in[5];
    const float* Wo     = (const float*)d_in[6];
    float* out = (float*)d_out;

    int KV = in_sizes[1] / (NB * NH * HD);
    int S = KV + NQ;
    if (S > SMAX) S = SMAX;
    int mo = S - (int)((double)S * 0.9);
    int cap = (S < 128) ? S : 128;
    int nrem = (cap > mo) ? cap : mo;
    if (nrem > 500) nrem = 500;

    int zmax = NROWS * NCOLS;
    if (out_size > zmax) zmax = out_size;
    int zb = (zmax + 255) / 256;
    int rb = (S + 3) / 4;
    init_kernel<<<zb + rb, 256>>>(out, out_size, zb, S);
    proj_qkv<<<dim3(NCOLS / 1024, KSPLIT), 256>>>(hid, Wq, Wk, Wv);
    rope_qkv<<<16, 256>>>(S);
    draft_kernel<<<dim3((S + TS - 1) / TS, NB * NH), 128>>>(kcache, S, KV);
    topk_thresh<<<NROWS_ATT, 256>>>(S, nrem);
    attn_gather<<<dim3(NROWS_ATT, VSPLIT), 256>>>(vcache, S, KV);
    proj_out<<<dim3(DMODEL / 1024, KSPLIT), 256>>>(Wo, out);
}